// round 1
// baseline (speedup 1.0000x reference)
#include <cuda_runtime.h>
#include <math.h>

// Problem constants
#define BB   8
#define NN   2
#define NP   16        // B*N pairs
#define DD   256       // K dim
#define TL   500       // T
#define SPK  2000
#define SPK_PAD 2048

// GEMM tile config
#define MT 64          // t-rows per CTA
#define MS 64          // speaker chunk
#define BSTRIDE 68     // padded Bs row stride (floats), 68*4B multiple of 16 -> float4 ok

__device__ double g_sum_lse;
__device__ double g_sum_dmin;
__device__ float  g_Esq[SPK_PAD];
__device__ float  g_Hsq[NP * TL];

// ---- int64-vs-int32 sniff for S (JAX may silently downcast int64->int32) ----
__device__ __forceinline__ bool s_is_64(const void* Sv) {
    const long long* S = (const long long*)Sv;
    bool ok = true;
#pragma unroll
    for (int i = 0; i < 8; ++i) {
        long long v = S[i];
        if (v < 0 || v >= (long long)SPK) ok = false;
    }
    return ok;
}
__device__ __forceinline__ long long load_sid(const void* Sv, int idx, bool is64) {
    if (is64) return ((const long long*)Sv)[idx];
    return (long long)((const int*)Sv)[idx];
}

// ---------------------------------------------------------------------------
// Prologue: zero accumulators, Esq (padded with +1e30 so padded cols vanish in
// LSE), Hsq, and the E_S[:,:,:,0] output block.
// ---------------------------------------------------------------------------
__global__ void prologue_kernel(const float* __restrict__ H,
                                const void*  __restrict__ Sv,
                                const float* __restrict__ E,
                                float* __restrict__ out) {
    int idx = blockIdx.x * blockDim.x + threadIdx.x;
    if (idx == 0) { g_sum_lse = 0.0; g_sum_dmin = 0.0; }

    if (idx < SPK_PAD) {
        if (idx < SPK) {
            const float* e = E + (size_t)idx * DD;
            float s = 0.f;
#pragma unroll 8
            for (int d = 0; d < DD; ++d) { float v = e[d]; s = fmaf(v, v, s); }
            g_Esq[idx] = s;
        } else {
            g_Esq[idx] = 1e30f;  // -> v = -alpha*1e30, exp underflows to 0
        }
    }

    if (idx < NP * TL) {
        int p = idx / TL, t = idx % TL;
        const float* h = H + (size_t)p * DD * TL + t;
        float s = 0.f;
#pragma unroll 8
        for (int d = 0; d < DD; ++d) { float v = h[d * TL]; s = fmaf(v, v, s); }
        g_Hsq[idx] = s;
    }

    if (idx < NP * DD) {                 // E_S[:,:,:,0] -> out[(b*2+n)*256 + d]
        bool is64 = s_is_64(Sv);
        int pn = idx >> 8, d = idx & 255;
        long long s = load_sid(Sv, pn * TL + 0, is64);
        out[idx] = E[(size_t)s * DD + d];
    }
}

// ---------------------------------------------------------------------------
// Dmin: per (b,t), 4 squared distances, min over the two alignments.
// ---------------------------------------------------------------------------
__global__ void dmin_kernel(const float* __restrict__ H,
                            const void*  __restrict__ Sv,
                            const float* __restrict__ E,
                            const float* __restrict__ alpha_p,
                            const float* __restrict__ beta_p) {
    int idx = blockIdx.x * blockDim.x + threadIdx.x;
    if (idx >= BB * TL) return;
    bool is64 = s_is_64(Sv);
    int b = idx / TL, t = idx % TL;
    long long sv0 = load_sid(Sv, (b * 2 + 0) * TL + t, is64);
    long long sv1 = load_sid(Sv, (b * 2 + 1) * TL + t, is64);
    const float* h0 = H + (size_t)(b * 2 + 0) * DD * TL + t;
    const float* h1 = H + (size_t)(b * 2 + 1) * DD * TL + t;
    const float* e0 = E + (size_t)sv0 * DD;
    const float* e1 = E + (size_t)sv1 * DD;
    float a00 = 0.f, a01 = 0.f, a10 = 0.f, a11 = 0.f;
#pragma unroll 4
    for (int d = 0; d < DD; ++d) {
        float x0 = h0[d * TL], x1 = h1[d * TL];
        float y0 = e0[d],      y1 = e1[d];
        float u;
        u = x0 - y0; a00 = fmaf(u, u, a00);
        u = x0 - y1; a01 = fmaf(u, u, a01);
        u = x1 - y0; a10 = fmaf(u, u, a10);
        u = x1 - y1; a11 = fmaf(u, u, a11);
    }
    float p0 = a00 + a11, p1 = a01 + a10;
    float dmin = fminf(p0, p1);
    float val = fmaf(-alpha_p[0], dmin, beta_p[0]);
    atomicAdd(&g_sum_dmin, (double)val);
}

// ---------------------------------------------------------------------------
// Fused GEMM + online LSE.
//   grid = (8 t-tiles, 16 pairs), 256 threads, 4x4 register tiles.
//   As = full-K H tile [256][64] (loaded once), Bs = E chunk [256][68].
//   lse_row = m + log(l) - alpha*Hsq + beta ; sum into g_sum_lse.
// ---------------------------------------------------------------------------
__global__ void __launch_bounds__(256)
gemm_lse_kernel(const float* __restrict__ H, const float* __restrict__ E,
                const float* __restrict__ alpha_p, const float* __restrict__ beta_p) {
    extern __shared__ float sm[];
    float* As = sm;                // [256][64]
    float* Bs = sm + DD * MT;      // [256][BSTRIDE]

    int tid = threadIdx.x;
    int tx = tid & 15, ty = tid >> 4;
    int p  = blockIdx.y;
    int t0 = blockIdx.x * MT;
    float alpha = alpha_p[0];
    float beta  = beta_p[0];
    float a2 = 2.f * alpha;

    const float* Hp = H + (size_t)p * DD * TL;
    for (int idx = tid; idx < DD * MT; idx += 256) {
        int k = idx >> 6, t = idx & 63;
        int tg = t0 + t;
        As[idx] = (tg < TL) ? Hp[k * TL + tg] : 0.f;
    }

    float m[4], l[4];
#pragma unroll
    for (int i = 0; i < 4; ++i) { m[i] = -INFINITY; l[i] = 0.f; }

    for (int s0 = 0; s0 < SPK_PAD; s0 += MS) {
        __syncthreads();
        // Load E chunk: global-coalesced on k, store transposed [k][s] (padded).
        for (int idx = tid; idx < MS * DD; idx += 256) {
            int k = idx & 255, s = idx >> 8;
            int sg = s0 + s;
            Bs[k * BSTRIDE + s] = (sg < SPK) ? E[(size_t)sg * DD + k] : 0.f;
        }
        __syncthreads();

        float acc[4][4];
#pragma unroll
        for (int i = 0; i < 4; ++i)
#pragma unroll
            for (int j = 0; j < 4; ++j) acc[i][j] = 0.f;

#pragma unroll 8
        for (int k = 0; k < DD; ++k) {
            float4 a = *(const float4*)&As[k * MT + ty * 4];
            float4 b = *(const float4*)&Bs[k * BSTRIDE + tx * 4];
            acc[0][0] = fmaf(a.x, b.x, acc[0][0]);
            acc[0][1] = fmaf(a.x, b.y, acc[0][1]);
            acc[0][2] = fmaf(a.x, b.z, acc[0][2]);
            acc[0][3] = fmaf(a.x, b.w, acc[0][3]);
            acc[1][0] = fmaf(a.y, b.x, acc[1][0]);
            acc[1][1] = fmaf(a.y, b.y, acc[1][1]);
            acc[1][2] = fmaf(a.y, b.z, acc[1][2]);
            acc[1][3] = fmaf(a.y, b.w, acc[1][3]);
            acc[2][0] = fmaf(a.z, b.x, acc[2][0]);
            acc[2][1] = fmaf(a.z, b.y, acc[2][1]);
            acc[2][2] = fmaf(a.z, b.z, acc[2][2]);
            acc[2][3] = fmaf(a.z, b.w, acc[2][3]);
            acc[3][0] = fmaf(a.w, b.x, acc[3][0]);
            acc[3][1] = fmaf(a.w, b.y, acc[3][1]);
            acc[3][2] = fmaf(a.w, b.z, acc[3][2]);
            acc[3][3] = fmaf(a.w, b.w, acc[3][3]);
        }

        float vb[4];
#pragma unroll
        for (int j = 0; j < 4; ++j) vb[j] = -alpha * g_Esq[s0 + tx * 4 + j];

#pragma unroll
        for (int i = 0; i < 4; ++i) {
            float v0 = fmaf(a2, acc[i][0], vb[0]);
            float v1 = fmaf(a2, acc[i][1], vb[1]);
            float v2 = fmaf(a2, acc[i][2], vb[2]);
            float v3 = fmaf(a2, acc[i][3], vb[3]);
            float vm = fmaxf(fmaxf(v0, v1), fmaxf(v2, v3));
            float nm = fmaxf(m[i], vm);
            float sc = __expf(m[i] - nm);   // exp(-inf)=0 on first chunk
            float e  = __expf(v0 - nm) + __expf(v1 - nm) +
                       __expf(v2 - nm) + __expf(v3 - nm);
            l[i] = fmaf(l[i], sc, e);
            m[i] = nm;
        }
    }

    // Combine (m,l) across the 16 tx-lanes (same half-warp).
#pragma unroll
    for (int i = 0; i < 4; ++i) {
#pragma unroll
        for (int off = 8; off > 0; off >>= 1) {
            float m2 = __shfl_xor_sync(0xFFFFFFFFu, m[i], off, 16);
            float l2 = __shfl_xor_sync(0xFFFFFFFFu, l[i], off, 16);
            float nm = fmaxf(m[i], m2);
            l[i] = l[i] * __expf(m[i] - nm) + l2 * __expf(m2 - nm);
            m[i] = nm;
        }
    }

    __shared__ double bsum;
    __syncthreads();
    if (tid == 0) bsum = 0.0;
    __syncthreads();
    if (tx == 0) {
        double accd = 0.0;
#pragma unroll
        for (int i = 0; i < 4; ++i) {
            int t = t0 + ty * 4 + i;
            if (t < TL) {
                float lse = m[i] + __logf(l[i]);
                float val = lse + fmaf(-alpha, g_Hsq[p * TL + t], beta);
                accd += (double)val;
            }
        }
        atomicAdd(&bsum, accd);
    }
    __syncthreads();
    if (tid == 0) atomicAdd(&g_sum_lse, bsum);
}

// ---------------------------------------------------------------------------
__global__ void finalize_kernel(float* __restrict__ out, int loss_idx) {
    out[loss_idx] = (float)(-(g_sum_dmin / (double)(BB * TL)) +
                             (g_sum_lse / (double)(NP * TL)));
}

extern "C" void kernel_launch(void* const* d_in, const int* in_sizes, int n_in,
                              void* d_out, int out_size) {
    const float* H     = (const float*)d_in[0];
    const void*  S     = (const void*)d_in[1];
    const float* E     = (const float*)d_in[2];
    const float* alpha = (const float*)d_in[3];
    const float* beta  = (const float*)d_in[4];
    float* out = (float*)d_out;

    size_t smem = (size_t)(DD * MT + DD * BSTRIDE) * sizeof(float);  // 132 KB
    cudaFuncSetAttribute(gemm_lse_kernel,
                         cudaFuncAttributeMaxDynamicSharedMemorySize, (int)smem);

    prologue_kernel<<<32, 256>>>(H, S, E, out);                 // 8192 threads
    dmin_kernel<<<16, 256>>>(H, S, E, alpha, beta);             // 4000 (b,t)
    gemm_lse_kernel<<<dim3(8, 16), 256, smem>>>(H, E, alpha, beta);
    finalize_kernel<<<1, 1>>>(out, out_size - 1);
}

// round 4
// speedup vs baseline: 3.7334x; 3.7334x over previous
#include <cuda_runtime.h>
#include <cuda_bf16.h>
#include <math.h>
#include <stdint.h>

#define BB   8
#define NP   16
#define DD   256
#define TL   500
#define SPK  2000
#define SPK_PAD 2048
#define MROWS 8064
#define MT 128
#define NC 64
#define NCHUNK 16
#define LOG2E 1.4426950408889634f
#define LN2   0.6931471805599453f

#define RS 264                      // smem row stride in bf16 (528 B)
#define SM_AHI 0                    // 128*264*2 = 67584
#define SM_ALO 67584
#define SM_BHI 135168               // 64*264*2 = 33792
#define SM_BLO 168960
#define SM_TOTAL 202752

// ---------------- device globals ----------------
__device__ double g_sum_lse;
__device__ double g_sum_dmin;
__device__ float  g_Esq[SPK_PAD];
__device__ float  g_Hsq[MROWS];
__device__ float  g_pm[2 * MROWS];
__device__ float  g_pl[2 * MROWS];

// ---------------- helpers ----------------
__device__ __forceinline__ uint32_t smem_u32(const void* p) {
    uint32_t a;
    asm("{ .reg .u64 t; cvta.to.shared.u64 t, %1; cvt.u32.u64 %0, t; }" : "=r"(a) : "l"(p));
    return a;
}
__device__ __forceinline__ float ex2(float x) {
    float y; asm("ex2.approx.f32 %0, %1;" : "=f"(y) : "f"(x)); return y;
}
__device__ __forceinline__ void ldm4(uint32_t& r0, uint32_t& r1, uint32_t& r2,
                                     uint32_t& r3, uint32_t a) {
    asm volatile("ldmatrix.sync.aligned.m8n8.x4.shared.b16 {%0,%1,%2,%3}, [%4];"
                 : "=r"(r0), "=r"(r1), "=r"(r2), "=r"(r3) : "r"(a));
}
__device__ __forceinline__ void mma16816(float* c, uint32_t a0, uint32_t a1,
                                         uint32_t a2, uint32_t a3,
                                         uint32_t b0, uint32_t b1) {
    asm volatile("mma.sync.aligned.m16n8k16.row.col.f32.bf16.bf16.f32 "
                 "{%0,%1,%2,%3}, {%4,%5,%6,%7}, {%8,%9}, {%0,%1,%2,%3};"
                 : "+f"(c[0]), "+f"(c[1]), "+f"(c[2]), "+f"(c[3])
                 : "r"(a0), "r"(a1), "r"(a2), "r"(a3), "r"(b0), "r"(b1));
}
__device__ __forceinline__ uint32_t pack_bf2(float x0, float x1) {
    __nv_bfloat16 h0 = __float2bfloat16(x0), h1 = __float2bfloat16(x1);
    return (uint32_t)__bfloat16_as_ushort(h0) |
           ((uint32_t)__bfloat16_as_ushort(h1) << 16);
}

// ---- int64-vs-int32 sniff for S ----
__device__ __forceinline__ bool s_is_64(const void* Sv) {
    const long long* S = (const long long*)Sv;
    bool ok = true;
#pragma unroll
    for (int i = 0; i < 8; ++i) { long long v = S[i]; if (v < 0 || v >= (long long)SPK) ok = false; }
    return ok;
}
__device__ __forceinline__ long long load_sid(const void* Sv, int idx, bool is64) {
    if (is64) return ((const long long*)Sv)[idx];
    return (long long)((const int*)Sv)[idx];
}

// ---------------------------------------------------------------------------
// Prologue: zero sums, Esq (padded 1e30), E_S[:,:,:,0] output. Warp-per-task.
// ---------------------------------------------------------------------------
__global__ void prologue_kernel(const void* __restrict__ Sv,
                                const float* __restrict__ E,
                                float* __restrict__ out) {
    int gw = (blockIdx.x * blockDim.x + threadIdx.x) >> 5;
    int lane = threadIdx.x & 31;
    if (gw < SPK_PAD) {
        int s = gw;
        if (s < SPK) {
            const float* e = E + (size_t)s * DD;
            float a = 0.f;
#pragma unroll
            for (int i = 0; i < 8; ++i) { float v = e[lane + i * 32]; a = fmaf(v, v, a); }
#pragma unroll
            for (int off = 16; off > 0; off >>= 1) a += __shfl_xor_sync(0xFFFFFFFFu, a, off);
            if (lane == 0) g_Esq[s] = a;
        } else if (lane == 0) {
            g_Esq[s] = 1e30f;
        }
    } else if (gw < SPK_PAD + 128) {
        bool is64 = s_is_64(Sv);
        int idx = (gw - SPK_PAD) * 32 + lane;   // < 4096
        int pn = idx >> 8, d = idx & 255;
        long long s = load_sid(Sv, pn * TL, is64);
        out[idx] = E[(size_t)s * DD + d];
    } else if (gw == SPK_PAD + 128 && lane == 0) {
        g_sum_lse = 0.0; g_sum_dmin = 0.0;
    }
}

// ---------------------------------------------------------------------------
// Dmin: warp per (b,t).
// ---------------------------------------------------------------------------
__global__ void dmin_kernel(const float* __restrict__ H,
                            const void*  __restrict__ Sv,
                            const float* __restrict__ E,
                            const float* __restrict__ alpha_p,
                            const float* __restrict__ beta_p) {
    __shared__ double bsum;
    if (threadIdx.x == 0) bsum = 0.0;
    __syncthreads();

    int gw = (blockIdx.x * blockDim.x + threadIdx.x) >> 5;
    int lane = threadIdx.x & 31;
    if (gw < BB * TL) {
        bool is64 = s_is_64(Sv);
        int b = gw / TL, t = gw % TL;
        long long sv0 = load_sid(Sv, (b * 2 + 0) * TL + t, is64);
        long long sv1 = load_sid(Sv, (b * 2 + 1) * TL + t, is64);
        const float* h0 = H + (size_t)(b * 2 + 0) * DD * TL + t;
        const float* h1 = H + (size_t)(b * 2 + 1) * DD * TL + t;
        const float* e0 = E + (size_t)sv0 * DD;
        const float* e1 = E + (size_t)sv1 * DD;
        float a00 = 0.f, a01 = 0.f, a10 = 0.f, a11 = 0.f;
#pragma unroll
        for (int i = 0; i < 8; ++i) {
            int d = lane + i * 32;
            float x0 = h0[(size_t)d * TL], x1 = h1[(size_t)d * TL];
            float y0 = e0[d], y1 = e1[d];
            float u;
            u = x0 - y0; a00 = fmaf(u, u, a00);
            u = x0 - y1; a01 = fmaf(u, u, a01);
            u = x1 - y0; a10 = fmaf(u, u, a10);
            u = x1 - y1; a11 = fmaf(u, u, a11);
        }
#pragma unroll
        for (int off = 16; off > 0; off >>= 1) {
            a00 += __shfl_xor_sync(0xFFFFFFFFu, a00, off);
            a01 += __shfl_xor_sync(0xFFFFFFFFu, a01, off);
            a10 += __shfl_xor_sync(0xFFFFFFFFu, a10, off);
            a11 += __shfl_xor_sync(0xFFFFFFFFu, a11, off);
        }
        if (lane == 0) {
            float dmin = fminf(a00 + a11, a01 + a10);
            float val = fmaf(-alpha_p[0], dmin, beta_p[0]);
            atomicAdd(&bsum, (double)val);
        }
    }
    __syncthreads();
    if (threadIdx.x == 0) atomicAdd(&g_sum_dmin, bsum);
}

// ---------------------------------------------------------------------------
// mma.sync GEMM + online LSE (log2 domain).
// grid (63 m-tiles, 2 halves), 256 threads = 8 warps. Warp = 16 rows x 64 cols.
// A tile 128x256 (hi+lo bf16), B chunk 64x256 (hi+lo), 3-term split MMA.
// ---------------------------------------------------------------------------
__global__ void __launch_bounds__(256, 1)
gemm_lse_kernel(const float* __restrict__ H, const float* __restrict__ E,
                const float* __restrict__ alpha_p, const float* __restrict__ beta_p) {
    extern __shared__ char smem[];
    uint32_t sb = smem_u32(smem);
    int tid = threadIdx.x;
    int lane = tid & 31, wid = tid >> 5;
    int bx = blockIdx.x;
    int half = blockIdx.y;

    const float alpha = alpha_p[0];
    const float a2l = 2.f * alpha * LOG2E;
    const float al  = alpha * LOG2E;

    // ---- build A tile (rows = 128, split k across tid>>7) + Hsq ----
    {
        int row = tid & 127, kh = tid >> 7;
        int m = bx * MT + row;
        bool valid = (m < NP * TL);
        const float* hb = nullptr;
        if (valid) {
            int p = m / TL, t = m - p * TL;
            hb = H + ((size_t)p * DD) * TL + t;
        }
        float hsq = 0.f;
#pragma unroll 2
        for (int kb = 0; kb < 16; ++kb) {
            int k0 = kh * 128 + kb * 8;
            uint32_t ph[4], pl[4];
#pragma unroll
            for (int j = 0; j < 4; ++j) {
                float x0 = valid ? hb[(size_t)(k0 + 2 * j) * TL] : 0.f;
                float x1 = valid ? hb[(size_t)(k0 + 2 * j + 1) * TL] : 0.f;
                hsq = fmaf(x0, x0, hsq);
                hsq = fmaf(x1, x1, hsq);
                __nv_bfloat16 h0 = __float2bfloat16(x0), h1 = __float2bfloat16(x1);
                float r0 = x0 - __bfloat162float(h0);
                float r1 = x1 - __bfloat162float(h1);
                ph[j] = (uint32_t)__bfloat16_as_ushort(h0) |
                        ((uint32_t)__bfloat16_as_ushort(h1) << 16);
                pl[j] = pack_bf2(r0, r1);
            }
            uint32_t off = (uint32_t)(row * RS + k0) * 2;
            *(uint4*)(smem + SM_AHI + off) = make_uint4(ph[0], ph[1], ph[2], ph[3]);
            *(uint4*)(smem + SM_ALO + off) = make_uint4(pl[0], pl[1], pl[2], pl[3]);
        }
        // combine k-half partials via smem scratch (B area, before first B write)
        float* pbuf = (float*)(smem + SM_BHI);
        pbuf[tid] = hsq;
        __syncthreads();
        if (half == 0 && tid < 128 && valid) g_Hsq[m] = pbuf[tid] + pbuf[tid + 128];
    }

    // ---- fragment smem offsets ----
    int r = lane & 7, seg = lane >> 3;
    uint32_t a_base = (uint32_t)((wid * 16 + (seg & 1) * 8 + r) * RS + (seg >> 1) * 8) * 2;
    uint32_t b_base[4];
#pragma unroll
    for (int p = 0; p < 4; ++p)
        b_base[p] = (uint32_t)((p * 16 + (seg >> 1) * 8 + r) * RS + (seg & 1) * 8) * 2;

    float mrun[2] = {-1e30f, -1e30f};
    float lrun[2] = {0.f, 0.f};
    int sbase = half * 1024;

    for (int c = 0; c < NCHUNK; ++c) {
        int s0 = sbase + c * NC;
        __syncthreads();   // prev chunk's ldmatrix (or hsq scratch reads) done
        // ---- build B chunk: 64 speakers x 256 k, hi+lo; unit = 8 k-elems ----
#pragma unroll
        for (int i = 0; i < 8; ++i) {
            int idx = tid + i * 256;            // 2048 units total
            int s = idx >> 5, u = idx & 31;     // 32 units (of 8 elems) per speaker
            int sg = s0 + s;
            int k0 = u * 8;
            float4 va = make_float4(0.f, 0.f, 0.f, 0.f);
            float4 vb = make_float4(0.f, 0.f, 0.f, 0.f);
            if (sg < SPK) {
                const float* ep = E + (size_t)sg * DD + k0;
                va = *(const float4*)ep;
                vb = *(const float4*)(ep + 4);
            }
            uint32_t ph[4], pl[4];
            const float xs[8] = {va.x, va.y, va.z, va.w, vb.x, vb.y, vb.z, vb.w};
#pragma unroll
            for (int j = 0; j < 4; ++j) {
                float x0 = xs[2 * j], x1 = xs[2 * j + 1];
                __nv_bfloat16 h0 = __float2bfloat16(x0), h1 = __float2bfloat16(x1);
                ph[j] = (uint32_t)__bfloat16_as_ushort(h0) |
                        ((uint32_t)__bfloat16_as_ushort(h1) << 16);
                pl[j] = pack_bf2(x0 - __bfloat162float(h0), x1 - __bfloat162float(h1));
            }
            uint32_t off = (uint32_t)(s * RS + k0) * 2;
            *(uint4*)(smem + SM_BHI + off) = make_uint4(ph[0], ph[1], ph[2], ph[3]);
            *(uint4*)(smem + SM_BLO + off) = make_uint4(pl[0], pl[1], pl[2], pl[3]);
        }
        __syncthreads();

        // ---- MMA mainloop over k ----
        float acc[8][4];
#pragma unroll
        for (int n = 0; n < 8; ++n)
#pragma unroll
            for (int q = 0; q < 4; ++q) acc[n][q] = 0.f;

#pragma unroll 4
        for (int ks = 0; ks < 16; ++ks) {
            uint32_t ka = (uint32_t)ks * 32;
            uint32_t ah0, ah1, ah2, ah3, al0, al1, al2, al3;
            ldm4(ah0, ah1, ah2, ah3, sb + SM_AHI + a_base + ka);
            ldm4(al0, al1, al2, al3, sb + SM_ALO + a_base + ka);
#pragma unroll
            for (int p = 0; p < 4; ++p) {
                uint32_t bh0, bh1, bh2, bh3, bl0, bl1, bl2, bl3;
                ldm4(bh0, bh1, bh2, bh3, sb + SM_BHI + b_base[p] + ka);
                ldm4(bl0, bl1, bl2, bl3, sb + SM_BLO + b_base[p] + ka);
                mma16816(acc[2 * p],     ah0, ah1, ah2, ah3, bh0, bh1);
                mma16816(acc[2 * p],     ah0, ah1, ah2, ah3, bl0, bl1);
                mma16816(acc[2 * p],     al0, al1, al2, al3, bh0, bh1);
                mma16816(acc[2 * p + 1], ah0, ah1, ah2, ah3, bh2, bh3);
                mma16816(acc[2 * p + 1], ah0, ah1, ah2, ah3, bl2, bl3);
                mma16816(acc[2 * p + 1], al0, al1, al2, al3, bh2, bh3);
            }
        }

        // ---- epilogue: online LSE (log2 domain) ----
        int qn = (lane & 3) * 2;
        float nml[16];
#pragma unroll
        for (int nt = 0; nt < 8; ++nt) {
            nml[2 * nt]     = -al * g_Esq[s0 + nt * 8 + qn];
            nml[2 * nt + 1] = -al * g_Esq[s0 + nt * 8 + qn + 1];
        }
#pragma unroll
        for (int h = 0; h < 2; ++h) {
            float v[16], vmax = -1e30f;
#pragma unroll
            for (int nt = 0; nt < 8; ++nt) {
#pragma unroll
                for (int cc = 0; cc < 2; ++cc) {
                    float vv = fmaf(a2l, acc[nt][h * 2 + cc], nml[2 * nt + cc]);
                    v[2 * nt + cc] = vv;
                    vmax = fmaxf(vmax, vv);
                }
            }
            float nm = fmaxf(mrun[h], vmax);
            float e = 0.f;
#pragma unroll
            for (int j = 0; j < 16; ++j) e += ex2(v[j] - nm);
            lrun[h] = fmaf(lrun[h], ex2(mrun[h] - nm), e);
            mrun[h] = nm;
        }
    }

    // ---- reduce across the 4 lanes sharing each row, write partials ----
#pragma unroll
    for (int h = 0; h < 2; ++h) {
#pragma unroll
        for (int off = 1; off <= 2; off <<= 1) {
            float m2 = __shfl_xor_sync(0xFFFFFFFFu, mrun[h], off);
            float l2 = __shfl_xor_sync(0xFFFFFFFFu, lrun[h], off);
            float nm = fmaxf(mrun[h], m2);
            lrun[h] = lrun[h] * ex2(mrun[h] - nm) + l2 * ex2(m2 - nm);
            mrun[h] = nm;
        }
        if ((lane & 3) == 0) {
            int rw = wid * 16 + h * 8 + (lane >> 2);
            int gm = bx * MT + rw;
            g_pm[half * MROWS + gm] = mrun[h];
            g_pl[half * MROWS + gm] = lrun[h];
        }
    }
}

// ---------------------------------------------------------------------------
// Merge halves -> lse per row -> sum.
// ---------------------------------------------------------------------------
__global__ void merge_kernel(const float* __restrict__ alpha_p,
                             const float* __restrict__ beta_p) {
    __shared__ double bsum;
    if (threadIdx.x == 0) bsum = 0.0;
    __syncthreads();
    int idx = blockIdx.x * blockDim.x + threadIdx.x;
    double v = 0.0;
    if (idx < NP * TL) {
        float m0 = g_pm[idx],         l0 = g_pl[idx];
        float m1 = g_pm[MROWS + idx], l1 = g_pl[MROWS + idx];
        float M = fmaxf(m0, m1);
        float L = l0 * ex2(m0 - M) + l1 * ex2(m1 - M);
        float lse = (M + log2f(L)) * LN2;
        v = (double)(lse + fmaf(-alpha_p[0], g_Hsq[idx], beta_p[0]));
    }
    atomicAdd(&bsum, v);
    __syncthreads();
    if (threadIdx.x == 0) atomicAdd(&g_sum_lse, bsum);
}

__global__ void finalize_kernel(float* __restrict__ out, int loss_idx) {
    out[loss_idx] = (float)(-(g_sum_dmin / (double)(BB * TL)) +
                             (g_sum_lse / (double)(NP * TL)));
}

// ---------------------------------------------------------------------------
extern "C" void kernel_launch(void* const* d_in, const int* in_sizes, int n_in,
                              void* d_out, int out_size) {
    const float* H     = (const float*)d_in[0];
    const void*  S     = (const void*)d_in[1];
    const float* E     = (const float*)d_in[2];
    const float* alpha = (const float*)d_in[3];
    const float* beta  = (const float*)d_in[4];
    float* out = (float*)d_out;

    cudaFuncSetAttribute(gemm_lse_kernel,
                         cudaFuncAttributeMaxDynamicSharedMemorySize, SM_TOTAL);

    prologue_kernel<<<(SPK_PAD + 129 + 7) / 8, 256>>>(S, E, out);
    dmin_kernel<<<(BB * TL + 7) / 8, 256>>>(H, S, E, alpha, beta);
    gemm_lse_kernel<<<dim3(63, 2), 256, SM_TOTAL>>>(H, E, alpha, beta);
    merge_kernel<<<(NP * TL + 255) / 256, 256>>>(alpha, beta);
    finalize_kernel<<<1, 1>>>(out, out_size - 1);
}

// round 5
// speedup vs baseline: 5.9732x; 1.5999x over previous
#include <cuda_runtime.h>
#include <cuda_bf16.h>
#include <math.h>
#include <stdint.h>

#define BB   8
#define NP   16
#define DD   256
#define TL   500
#define SPK  2000
#define SPK_PAD 2048
#define MROWS 8064
#define MT 128
#define NC 64
#define NCHUNK 16
#define LOG2E 1.4426950408889634f
#define LN2   0.6931471805599453f

#define RS 264                      // smem row stride in bf16 (528 B)
#define SM_AHI 0                    // 128*264*2 = 67584
#define SM_ALO 67584
#define SM_B0  135168               // 64*264*2 = 33792
#define SM_B1  168960
#define SM_SCR 202752               // 1024 B scratch (hsq reduce)
#define SM_TOTAL 203776

#define PRO_BLOCKS 272              // (2048 Esq/Ehi + 128 E_S out) warps / 8
#define DMIN_BLOCKS 500             // 4000 (b,t) warps / 8

// ---------------- device globals ----------------
__device__ float  g_Esq[SPK_PAD];
__device__ float  g_Hsq[MROWS];
__device__ float  g_pm[2 * MROWS];
__device__ float  g_pl[2 * MROWS];
__device__ double g_dmin_part[DMIN_BLOCKS];
__device__ __nv_bfloat16 g_Ehi[SPK_PAD * DD];

// ---------------- helpers ----------------
__device__ __forceinline__ uint32_t smem_u32(const void* p) {
    uint32_t a;
    asm("{ .reg .u64 t; cvta.to.shared.u64 t, %1; cvt.u32.u64 %0, t; }" : "=r"(a) : "l"(p));
    return a;
}
__device__ __forceinline__ float ex2(float x) {
    float y; asm("ex2.approx.f32 %0, %1;" : "=f"(y) : "f"(x)); return y;
}
__device__ __forceinline__ void ldm4(uint32_t& r0, uint32_t& r1, uint32_t& r2,
                                     uint32_t& r3, uint32_t a) {
    asm volatile("ldmatrix.sync.aligned.m8n8.x4.shared.b16 {%0,%1,%2,%3}, [%4];"
                 : "=r"(r0), "=r"(r1), "=r"(r2), "=r"(r3) : "r"(a));
}
__device__ __forceinline__ void mma16816(float* c, uint32_t a0, uint32_t a1,
                                         uint32_t a2, uint32_t a3,
                                         uint32_t b0, uint32_t b1) {
    asm volatile("mma.sync.aligned.m16n8k16.row.col.f32.bf16.bf16.f32 "
                 "{%0,%1,%2,%3}, {%4,%5,%6,%7}, {%8,%9}, {%0,%1,%2,%3};"
                 : "+f"(c[0]), "+f"(c[1]), "+f"(c[2]), "+f"(c[3])
                 : "r"(a0), "r"(a1), "r"(a2), "r"(a3), "r"(b0), "r"(b1));
}
__device__ __forceinline__ uint32_t pack_bf2(float x0, float x1) {
    __nv_bfloat16 h0 = __float2bfloat16(x0), h1 = __float2bfloat16(x1);
    return (uint32_t)__bfloat16_as_ushort(h0) |
           ((uint32_t)__bfloat16_as_ushort(h1) << 16);
}
__device__ __forceinline__ void cp16(uint32_t dst, const void* src) {
    asm volatile("cp.async.cg.shared.global [%0], [%1], 16;" :: "r"(dst), "l"(src));
}
#define CP_COMMIT() asm volatile("cp.async.commit_group;" ::: "memory")
#define CP_WAIT(N)  asm volatile("cp.async.wait_group %0;" :: "n"(N) : "memory")

// ---- int64-vs-int32 sniff for S ----
__device__ __forceinline__ bool s_is_64(const void* Sv) {
    const long long* S = (const long long*)Sv;
    bool ok = true;
#pragma unroll
    for (int i = 0; i < 8; ++i) { long long v = S[i]; if (v < 0 || v >= (long long)SPK) ok = false; }
    return ok;
}
__device__ __forceinline__ long long load_sid(const void* Sv, int idx, bool is64) {
    if (is64) return ((const long long*)Sv)[idx];
    return (long long)((const int*)Sv)[idx];
}

// ---------------------------------------------------------------------------
// Fused prologue + dmin. Blocks [0,PRO_BLOCKS): Esq + E_hi + E_S output.
// Blocks [PRO_BLOCKS, PRO_BLOCKS+DMIN_BLOCKS): dmin partial per block.
// ---------------------------------------------------------------------------
__global__ void __launch_bounds__(256)
pre_kernel(const float* __restrict__ H, const void* __restrict__ Sv,
           const float* __restrict__ E, const float* __restrict__ alpha_p,
           const float* __restrict__ beta_p, float* __restrict__ out) {
    int wid = threadIdx.x >> 5, lane = threadIdx.x & 31;

    if (blockIdx.x < PRO_BLOCKS) {
        int gw = blockIdx.x * 8 + wid;
        if (gw < SPK_PAD) {
            int s = gw;
            __nv_bfloat16* eh = g_Ehi + (size_t)s * DD;
            if (s < SPK) {
                const float* e = E + (size_t)s * DD;
                float a = 0.f;
#pragma unroll
                for (int i = 0; i < 8; ++i) {
                    float v = e[lane + i * 32];
                    a = fmaf(v, v, a);
                    eh[lane + i * 32] = __float2bfloat16(v);
                }
#pragma unroll
                for (int off = 16; off > 0; off >>= 1) a += __shfl_xor_sync(0xFFFFFFFFu, a, off);
                if (lane == 0) g_Esq[s] = a;
            } else {
#pragma unroll
                for (int i = 0; i < 8; ++i) eh[lane + i * 32] = __float2bfloat16(0.f);
                if (lane == 0) g_Esq[s] = 1e30f;
            }
        } else if (gw < SPK_PAD + 128) {
            bool is64 = s_is_64(Sv);
            int idx = (gw - SPK_PAD) * 32 + lane;   // < 4096
            int pn = idx >> 8, d = idx & 255;
            long long s = load_sid(Sv, pn * TL, is64);
            out[idx] = E[(size_t)s * DD + d];
        }
        return;
    }

    // ---- dmin part ----
    __shared__ double warr[8];
    int bd = blockIdx.x - PRO_BLOCKS;
    int gw = bd * 8 + wid;
    double val = 0.0;
    if (gw < BB * TL) {
        bool is64 = s_is_64(Sv);
        int b = gw / TL, t = gw % TL;
        long long sv0 = load_sid(Sv, (b * 2 + 0) * TL + t, is64);
        long long sv1 = load_sid(Sv, (b * 2 + 1) * TL + t, is64);
        const float* h0 = H + (size_t)(b * 2 + 0) * DD * TL + t;
        const float* h1 = H + (size_t)(b * 2 + 1) * DD * TL + t;
        const float* e0 = E + (size_t)sv0 * DD;
        const float* e1 = E + (size_t)sv1 * DD;
        float a00 = 0.f, a01 = 0.f, a10 = 0.f, a11 = 0.f;
#pragma unroll
        for (int i = 0; i < 8; ++i) {
            int d = lane + i * 32;
            float x0 = h0[(size_t)d * TL], x1 = h1[(size_t)d * TL];
            float y0 = e0[d], y1 = e1[d];
            float u;
            u = x0 - y0; a00 = fmaf(u, u, a00);
            u = x0 - y1; a01 = fmaf(u, u, a01);
            u = x1 - y0; a10 = fmaf(u, u, a10);
            u = x1 - y1; a11 = fmaf(u, u, a11);
        }
#pragma unroll
        for (int off = 16; off > 0; off >>= 1) {
            a00 += __shfl_xor_sync(0xFFFFFFFFu, a00, off);
            a01 += __shfl_xor_sync(0xFFFFFFFFu, a01, off);
            a10 += __shfl_xor_sync(0xFFFFFFFFu, a10, off);
            a11 += __shfl_xor_sync(0xFFFFFFFFu, a11, off);
        }
        float dmin = fminf(a00 + a11, a01 + a10);
        val = (double)fmaf(-alpha_p[0], dmin, beta_p[0]);
    }
    if (lane == 0) warr[wid] = val;
    __syncthreads();
    if (threadIdx.x == 0) {
        double s = 0.0;
#pragma unroll
        for (int w = 0; w < 8; ++w) s += warr[w];
        g_dmin_part[bd] = s;
    }
}

// ---------------------------------------------------------------------------
// mma.sync GEMM + online LSE. 2-term split (A hi/lo x B hi).
// grid (63, 2), 256 threads = 8 warps; warp = 16 rows x 64 cols.
// B chunks double-buffered via cp.async from precomputed g_Ehi.
// ---------------------------------------------------------------------------
__global__ void __launch_bounds__(256, 1)
gemm_lse_kernel(const float* __restrict__ H,
                const float* __restrict__ alpha_p, const float* __restrict__ beta_p) {
    extern __shared__ char smem[];
    uint32_t sb = smem_u32(smem);
    int tid = threadIdx.x;
    int lane = tid & 31, wid = tid >> 5;
    int bx = blockIdx.x;
    int half = blockIdx.y;
    int sbase = half * 1024;

    const float alpha = alpha_p[0];
    const float a2l = 2.f * alpha * LOG2E;
    const float al  = alpha * LOG2E;

    // ---- prefetch B chunk 0 (cp.async, overlaps A build) ----
    {
#pragma unroll
        for (int i = 0; i < 8; ++i) {
            int idx = tid + i * 256;            // 2048 16B units
            int s = idx >> 5, u = idx & 31;
            cp16(sb + SM_B0 + (uint32_t)(s * (RS * 2) + u * 16),
                 g_Ehi + (size_t)(sbase + s) * DD + u * 8);
        }
        CP_COMMIT();
    }

    // ---- build A tile (rows = 128, k split across tid>>7) + Hsq ----
    {
        int row = tid & 127, kh = tid >> 7;
        int m = bx * MT + row;
        bool valid = (m < NP * TL);
        const float* hb = nullptr;
        if (valid) {
            int p = m / TL, t = m - p * TL;
            hb = H + ((size_t)p * DD) * TL + t;
        }
        float hsq = 0.f;
#pragma unroll 2
        for (int kb = 0; kb < 16; ++kb) {
            int k0 = kh * 128 + kb * 8;
            uint32_t ph[4], pl[4];
#pragma unroll
            for (int j = 0; j < 4; ++j) {
                float x0 = valid ? hb[(size_t)(k0 + 2 * j) * TL] : 0.f;
                float x1 = valid ? hb[(size_t)(k0 + 2 * j + 1) * TL] : 0.f;
                hsq = fmaf(x0, x0, hsq);
                hsq = fmaf(x1, x1, hsq);
                __nv_bfloat16 h0 = __float2bfloat16(x0), h1 = __float2bfloat16(x1);
                ph[j] = (uint32_t)__bfloat16_as_ushort(h0) |
                        ((uint32_t)__bfloat16_as_ushort(h1) << 16);
                pl[j] = pack_bf2(x0 - __bfloat162float(h0), x1 - __bfloat162float(h1));
            }
            uint32_t off = (uint32_t)(row * RS + k0) * 2;
            *(uint4*)(smem + SM_AHI + off) = make_uint4(ph[0], ph[1], ph[2], ph[3]);
            *(uint4*)(smem + SM_ALO + off) = make_uint4(pl[0], pl[1], pl[2], pl[3]);
        }
        float* pbuf = (float*)(smem + SM_SCR);
        pbuf[tid] = hsq;
        __syncthreads();
        if (half == 0 && tid < 128 && valid) g_Hsq[m] = pbuf[tid] + pbuf[tid + 128];
    }

    // ---- fragment smem offsets ----
    int r = lane & 7, seg = lane >> 3;
    uint32_t a_base = (uint32_t)((wid * 16 + (seg & 1) * 8 + r) * RS + (seg >> 1) * 8) * 2;
    uint32_t b_base[4];
#pragma unroll
    for (int p = 0; p < 4; ++p)
        b_base[p] = (uint32_t)((p * 16 + (seg >> 1) * 8 + r) * RS + (seg & 1) * 8) * 2;

    float mrun[2] = {-1e30f, -1e30f};
    float lrun[2] = {0.f, 0.f};

    for (int c = 0; c < NCHUNK; ++c) {
        int s0 = sbase + c * NC;
        // prefetch next chunk into the other buffer
        if (c + 1 < NCHUNK) {
            uint32_t bb = ((c + 1) & 1) ? SM_B1 : SM_B0;
            int ns = s0 + NC;
#pragma unroll
            for (int i = 0; i < 8; ++i) {
                int idx = tid + i * 256;
                int s = idx >> 5, u = idx & 31;
                cp16(sb + bb + (uint32_t)(s * (RS * 2) + u * 16),
                     g_Ehi + (size_t)(ns + s) * DD + u * 8);
            }
            CP_COMMIT();
            CP_WAIT(1);
        } else {
            CP_WAIT(0);
        }
        __syncthreads();

        uint32_t bcur = sb + ((c & 1) ? SM_B1 : SM_B0);

        // ---- MMA mainloop over k: 2-term (Ah + Al) x Bh ----
        float acc[8][4];
#pragma unroll
        for (int n = 0; n < 8; ++n)
#pragma unroll
            for (int q = 0; q < 4; ++q) acc[n][q] = 0.f;

#pragma unroll 4
        for (int ks = 0; ks < 16; ++ks) {
            uint32_t ka = (uint32_t)ks * 32;
            uint32_t ah0, ah1, ah2, ah3, al0, al1, al2, al3;
            ldm4(ah0, ah1, ah2, ah3, sb + SM_AHI + a_base + ka);
            ldm4(al0, al1, al2, al3, sb + SM_ALO + a_base + ka);
#pragma unroll
            for (int p = 0; p < 4; ++p) {
                uint32_t bh0, bh1, bh2, bh3;
                ldm4(bh0, bh1, bh2, bh3, bcur + b_base[p] + ka);
                mma16816(acc[2 * p],     ah0, ah1, ah2, ah3, bh0, bh1);
                mma16816(acc[2 * p],     al0, al1, al2, al3, bh0, bh1);
                mma16816(acc[2 * p + 1], ah0, ah1, ah2, ah3, bh2, bh3);
                mma16816(acc[2 * p + 1], al0, al1, al2, al3, bh2, bh3);
            }
        }

        // ---- epilogue: online LSE (log2 domain) ----
        int qn = (lane & 3) * 2;
        float nml[16];
#pragma unroll
        for (int nt = 0; nt < 8; ++nt) {
            nml[2 * nt]     = -al * g_Esq[s0 + nt * 8 + qn];
            nml[2 * nt + 1] = -al * g_Esq[s0 + nt * 8 + qn + 1];
        }
#pragma unroll
        for (int h = 0; h < 2; ++h) {
            float v[16], vmax = -1e30f;
#pragma unroll
            for (int nt = 0; nt < 8; ++nt) {
#pragma unroll
                for (int cc = 0; cc < 2; ++cc) {
                    float vv = fmaf(a2l, acc[nt][h * 2 + cc], nml[2 * nt + cc]);
                    v[2 * nt + cc] = vv;
                    vmax = fmaxf(vmax, vv);
                }
            }
            float nm = fmaxf(mrun[h], vmax);
            float e = 0.f;
#pragma unroll
            for (int j = 0; j < 16; ++j) e += ex2(v[j] - nm);
            lrun[h] = fmaf(lrun[h], ex2(mrun[h] - nm), e);
            mrun[h] = nm;
        }
        __syncthreads();   // all warps done reading bcur before it is refilled
    }

    // ---- reduce across the 4 lanes sharing each row, write partials ----
#pragma unroll
    for (int h = 0; h < 2; ++h) {
#pragma unroll
        for (int off = 1; off <= 2; off <<= 1) {
            float m2 = __shfl_xor_sync(0xFFFFFFFFu, mrun[h], off);
            float l2 = __shfl_xor_sync(0xFFFFFFFFu, lrun[h], off);
            float nm = fmaxf(mrun[h], m2);
            lrun[h] = lrun[h] * ex2(mrun[h] - nm) + l2 * ex2(m2 - nm);
            mrun[h] = nm;
        }
        if ((lane & 3) == 0) {
            int rw = wid * 16 + h * 8 + (lane >> 2);
            int gm = bx * MT + rw;
            g_pm[half * MROWS + gm] = mrun[h];
            g_pl[half * MROWS + gm] = lrun[h];
        }
    }
}

// ---------------------------------------------------------------------------
// Single-block merge + finalize: rows -> lse sum; dmin partials -> sum; loss.
// ---------------------------------------------------------------------------
__global__ void __launch_bounds__(1024)
merge_kernel(const float* __restrict__ alpha_p, const float* __restrict__ beta_p,
             float* __restrict__ out, int loss_idx) {
    __shared__ double w_lse[32], w_dm[32];
    int tid = threadIdx.x, lane = tid & 31, wid = tid >> 5;
    float alpha = alpha_p[0], beta = beta_p[0];

    double acc = 0.0;
    for (int idx = tid; idx < NP * TL; idx += 1024) {
        float m0 = g_pm[idx],         l0 = g_pl[idx];
        float m1 = g_pm[MROWS + idx], l1 = g_pl[MROWS + idx];
        float M = fmaxf(m0, m1);
        float L = l0 * ex2(m0 - M) + l1 * ex2(m1 - M);
        float lse = (M + log2f(L)) * LN2;
        acc += (double)(lse + fmaf(-alpha, g_Hsq[idx], beta));
    }
    double dm = 0.0;
    for (int i = tid; i < DMIN_BLOCKS; i += 1024) dm += g_dmin_part[i];

#pragma unroll
    for (int off = 16; off > 0; off >>= 1) {
        acc += __shfl_down_sync(0xFFFFFFFFu, acc, off);
        dm  += __shfl_down_sync(0xFFFFFFFFu, dm, off);
    }
    if (lane == 0) { w_lse[wid] = acc; w_dm[wid] = dm; }
    __syncthreads();
    if (tid == 0) {
        double sl = 0.0, sd = 0.0;
#pragma unroll
        for (int w = 0; w < 32; ++w) { sl += w_lse[w]; sd += w_dm[w]; }
        out[loss_idx] = (float)(-(sd / (double)(BB * TL)) + (sl / (double)(NP * TL)));
    }
}

// ---------------------------------------------------------------------------
extern "C" void kernel_launch(void* const* d_in, const int* in_sizes, int n_in,
                              void* d_out, int out_size) {
    const float* H     = (const float*)d_in[0];
    const void*  S     = (const void*)d_in[1];
    const float* E     = (const float*)d_in[2];
    const float* alpha = (const float*)d_in[3];
    const float* beta  = (const float*)d_in[4];
    float* out = (float*)d_out;

    cudaFuncSetAttribute(gemm_lse_kernel,
                         cudaFuncAttributeMaxDynamicSharedMemorySize, SM_TOTAL);

    pre_kernel<<<PRO_BLOCKS + DMIN_BLOCKS, 256>>>(H, S, E, alpha, beta, out);
    gemm_lse_kernel<<<dim3(63, 2), 256, SM_TOTAL>>>(H, alpha, beta);
    merge_kernel<<<1, 1024>>>(alpha, beta, out, out_size - 1);
}